// round 1
// baseline (speedup 1.0000x reference)
#include <cuda_runtime.h>
#include <cuda_bf16.h>
#include <cstdint>

#define N_NODES 100000
#define N_EDGES 1600000
#define NF 64

// ---------------- scratch (static __device__ — no allocations allowed) ----------------
__device__ float g_aggr[(size_t)N_NODES * NF];
__device__ float g_h1[(size_t)N_NODES * NF];
__device__ float g_h2[(size_t)N_NODES * NF];
__device__ int   g_src[N_EDGES];
__device__ int   g_dst[N_EDGES];
__device__ int   g_deg[N_NODES];
__device__ double g_red[1];
__device__ int   g_is64[1];

// ---------------- edge dtype detection ----------------
// int64 layout => every odd 32-bit word is the (zero) high half. int32 layout =>
// odd words are random node ids; P(all 64 samples zero) ~ 1e-320.
__global__ void detect_kernel(const unsigned int* __restrict__ w, int* __restrict__ flag) {
    if (threadIdx.x == 0 && blockIdx.x == 0) {
        unsigned int acc = 0;
        #pragma unroll 1
        for (int i = 0; i < 64; i++) {
            unsigned int idx = 2u * (unsigned int)(i * 24999 + 13) + 1u;  // < 3.2M words
            acc |= w[idx];
        }
        *flag = (acc == 0u) ? 1 : 0;
    }
}

__global__ void zero_float_kernel(float* __restrict__ p, int n4) {
    int i = blockIdx.x * blockDim.x + threadIdx.x;
    if (i < n4) reinterpret_cast<float4*>(p)[i] = make_float4(0.f, 0.f, 0.f, 0.f);
}

__global__ void zero_misc_kernel(int* __restrict__ deg, double* __restrict__ red) {
    int i = blockIdx.x * blockDim.x + threadIdx.x;
    if (i < N_NODES) deg[i] = 0;
    if (i == 0) red[0] = 0.0;
}

__global__ void prep_kernel(const void* __restrict__ ei, int* __restrict__ esrc,
                            int* __restrict__ edst, int* __restrict__ deg,
                            const int* __restrict__ flag) {
    int e = blockIdx.x * blockDim.x + threadIdx.x;
    if (e >= N_EDGES) return;
    int s, d;
    if (*flag) {
        const long long* p = (const long long*)ei;
        s = (int)p[e];
        d = (int)p[N_EDGES + e];
    } else {
        const int* p = (const int*)ei;
        s = p[e];
        d = p[N_EDGES + e];
    }
    esrc[e] = s;
    edst[e] = d;
    atomicAdd(deg + s, 1);
}

// ---------------- scatter: aggr[dst] += feat[src], 64 f32 per edge ----------------
// One 16-byte chunk per thread: 16 threads per edge, vector reduction to L2.
__global__ void __launch_bounds__(256) scatter_kernel(const float* __restrict__ feat,
                                                      float* __restrict__ aggr,
                                                      const int* __restrict__ esrc,
                                                      const int* __restrict__ edst) {
    int idx = blockIdx.x * 256 + threadIdx.x;      // grid sized exactly E*16/256
    int e = idx >> 4;
    int c = (idx & 15) << 2;
    int s = __ldg(esrc + e);
    int d = __ldg(edst + e);
    float4 v = *reinterpret_cast<const float4*>(feat + (size_t)s * NF + c);
    float* p = aggr + (size_t)d * NF + c;
    asm volatile("red.global.add.v4.f32 [%0], {%1,%2,%3,%4};"
                 :: "l"(p), "f"(v.x), "f"(v.y), "f"(v.z), "f"(v.w) : "memory");
}

// ---------------- fused GEMM: out = act( A1@W1 + A2@W2 + b ) ----------------
// [N x 128] @ [128 x 64], K split as (A1,W1)[0:64) + (A2,W2)[64:128).
// Block: 64 rows x 64 cols, 256 threads, 4x4 register tile per thread.
__global__ void __launch_bounds__(256) fused_gemm_kernel(
    const float* __restrict__ A1, const float* __restrict__ A2,
    const float* __restrict__ W1, const float* __restrict__ W2,
    const float* __restrict__ bias, float* __restrict__ out,
    int n, int do_relu) {
    __shared__ float Ash[16][68];   // [k][row], pitch 68 floats (272B, 16B-aligned rows)
    __shared__ float Wsh[16][64];   // [k][col]
    __shared__ float bsh[64];

    const int tid = threadIdx.x;
    const int tx = tid & 15;        // col group
    const int ty = tid >> 4;        // row group
    const int row_base = blockIdx.x * 64;

    if (tid < 64) bsh[tid] = bias[tid];

    float acc[4][4];
    #pragma unroll
    for (int i = 0; i < 4; i++)
        #pragma unroll
        for (int j = 0; j < 4; j++) acc[i][j] = 0.f;

    const int lr = tid >> 2;            // 0..63: row this thread loads
    const int lk = (tid & 3) << 2;      // 0,4,8,12: k offset within chunk

    #pragma unroll 1
    for (int ch = 0; ch < 8; ch++) {
        const float* A = (ch < 4) ? A1 : A2;
        const float* W = (ch < 4) ? W1 : W2;
        const int k0 = (ch & 3) * 16;

        int grow = row_base + lr;
        if (grow >= n) grow = n - 1;
        float4 av = *reinterpret_cast<const float4*>(A + (size_t)grow * NF + k0 + lk);
        float4 wv = *reinterpret_cast<const float4*>(W + (size_t)(k0 + (tid >> 4)) * NF + (tid & 15) * 4);

        __syncthreads();
        Ash[lk + 0][lr] = av.x;
        Ash[lk + 1][lr] = av.y;
        Ash[lk + 2][lr] = av.z;
        Ash[lk + 3][lr] = av.w;
        *reinterpret_cast<float4*>(&Wsh[tid >> 4][(tid & 15) * 4]) = wv;
        __syncthreads();

        #pragma unroll
        for (int kk = 0; kk < 16; kk++) {
            float4 a = *reinterpret_cast<const float4*>(&Ash[kk][ty * 4]);
            float4 w = *reinterpret_cast<const float4*>(&Wsh[kk][tx * 4]);
            acc[0][0] += a.x * w.x; acc[0][1] += a.x * w.y; acc[0][2] += a.x * w.z; acc[0][3] += a.x * w.w;
            acc[1][0] += a.y * w.x; acc[1][1] += a.y * w.y; acc[1][2] += a.y * w.z; acc[1][3] += a.y * w.w;
            acc[2][0] += a.z * w.x; acc[2][1] += a.z * w.y; acc[2][2] += a.z * w.z; acc[2][3] += a.z * w.w;
            acc[3][0] += a.w * w.x; acc[3][1] += a.w * w.y; acc[3][2] += a.w * w.z; acc[3][3] += a.w * w.w;
        }
    }

    const int col = tx * 4;
    #pragma unroll
    for (int i = 0; i < 4; i++) {
        int r = row_base + ty * 4 + i;
        if (r < n) {
            float4 o;
            o.x = acc[i][0] + bsh[col + 0];
            o.y = acc[i][1] + bsh[col + 1];
            o.z = acc[i][2] + bsh[col + 2];
            o.w = acc[i][3] + bsh[col + 3];
            if (do_relu) {
                o.x = fmaxf(o.x, 0.f); o.y = fmaxf(o.y, 0.f);
                o.z = fmaxf(o.z, 0.f); o.w = fmaxf(o.w, 0.f);
            }
            *reinterpret_cast<float4*>(out + (size_t)r * NF + col) = o;
        }
    }
}

// ---------------- layer 3 (collapsed): sum_i deg[i]*(h2_i . wrel3) + (h2_i . wroot3) ----
__global__ void __launch_bounds__(256) final_kernel(const float* __restrict__ h2,
                                                    const int* __restrict__ deg,
                                                    const float* __restrict__ wrel3,
                                                    const float* __restrict__ wroot3,
                                                    double* __restrict__ red) {
    const int lane = threadIdx.x & 31;
    const int warp = threadIdx.x >> 5;
    const float wr0 = __ldg(wrel3 + lane),  wr1 = __ldg(wrel3 + 32 + lane);
    const float wo0 = __ldg(wroot3 + lane), wo1 = __ldg(wroot3 + 32 + lane);

    float local = 0.f;
    const int base = blockIdx.x * 64 + warp * 8;
    #pragma unroll 1
    for (int it = 0; it < 8; it++) {
        int i = base + it;
        if (i < N_NODES) {
            float a = h2[(size_t)i * NF + lane];
            float b = h2[(size_t)i * NF + 32 + lane];
            float v = a * wr0 + b * wr1;   // . wrel3
            float u = a * wo0 + b * wo1;   // . wroot3
            #pragma unroll
            for (int off = 16; off; off >>= 1) {
                v += __shfl_xor_sync(0xffffffffu, v, off);
                u += __shfl_xor_sync(0xffffffffu, u, off);
            }
            if (lane == 0) local += (float)deg[i] * v + u;
        }
    }
    __shared__ double sh[8];
    if (lane == 0) sh[warp] = (double)local;
    __syncthreads();
    if (threadIdx.x == 0) {
        double s = 0.0;
        #pragma unroll
        for (int w = 0; w < 8; w++) s += sh[w];
        atomicAdd(red, s);
    }
}

__global__ void write_out_kernel(float* __restrict__ out, const double* __restrict__ red,
                                 const float* __restrict__ b3) {
    if (threadIdx.x == 0 && blockIdx.x == 0)
        out[0] = (float)(red[0] / (double)N_NODES + (double)b3[0]);
}

// ---------------- launch ----------------
extern "C" void kernel_launch(void* const* d_in, const int* in_sizes, int n_in,
                              void* d_out, int out_size) {
    const float* x      = (const float*)d_in[0];
    const void*  ei     = d_in[1];
    const float* wrel1  = (const float*)d_in[2];
    const float* brel1  = (const float*)d_in[3];
    const float* wroot1 = (const float*)d_in[4];
    const float* wrel2  = (const float*)d_in[5];
    const float* brel2  = (const float*)d_in[6];
    const float* wroot2 = (const float*)d_in[7];
    const float* wrel3  = (const float*)d_in[8];
    const float* brel3  = (const float*)d_in[9];
    const float* wroot3 = (const float*)d_in[10];
    float* out = (float*)d_out;

    float *aggr, *h1, *h2;
    int *esrc, *edst, *deg, *is64;
    double* red;
    cudaGetSymbolAddress((void**)&aggr, g_aggr);
    cudaGetSymbolAddress((void**)&h1,   g_h1);
    cudaGetSymbolAddress((void**)&h2,   g_h2);
    cudaGetSymbolAddress((void**)&esrc, g_src);
    cudaGetSymbolAddress((void**)&edst, g_dst);
    cudaGetSymbolAddress((void**)&deg,  g_deg);
    cudaGetSymbolAddress((void**)&red,  g_red);
    cudaGetSymbolAddress((void**)&is64, g_is64);

    const int feat4 = (N_NODES * NF) / 4;                 // 1.6M float4
    const int zf_blocks = (feat4 + 255) / 256;
    const int scat_blocks = (N_EDGES * 16) / 256;         // exactly 100000
    const int gemm_blocks = (N_NODES + 63) / 64;          // 1563
    const int prep_blocks = (N_EDGES + 255) / 256;

    // prep
    detect_kernel<<<1, 32>>>((const unsigned int*)ei, is64);
    zero_misc_kernel<<<(N_NODES + 255) / 256, 256>>>(deg, red);
    prep_kernel<<<prep_blocks, 256>>>(ei, esrc, edst, deg, is64);

    // layer 1
    zero_float_kernel<<<zf_blocks, 256>>>(aggr, feat4);
    scatter_kernel<<<scat_blocks, 256>>>(x, aggr, esrc, edst);
    fused_gemm_kernel<<<gemm_blocks, 256>>>(aggr, x, wrel1, wroot1, brel1, h1, N_NODES, 1);

    // layer 2
    zero_float_kernel<<<zf_blocks, 256>>>(aggr, feat4);
    scatter_kernel<<<scat_blocks, 256>>>(h1, aggr, esrc, edst);
    fused_gemm_kernel<<<gemm_blocks, 256>>>(aggr, h1, wrel2, wroot2, brel2, h2, N_NODES, 1);

    // layer 3 collapsed into a degree-weighted reduction
    final_kernel<<<gemm_blocks, 256>>>(h2, deg, wrel3, wroot3, red);
    write_out_kernel<<<1, 32>>>(out, red, brel3);
}

// round 2
// speedup vs baseline: 1.3407x; 1.3407x over previous
#include <cuda_runtime.h>
#include <cuda_bf16.h>
#include <cstdint>

#define N_NODES 100000
#define N_EDGES 1600000
#define NF 64

// ---------------- scratch (static __device__ — no allocations allowed) ----------------
__device__ float g_aggr[(size_t)N_NODES * NF];
__device__ float g_h1[(size_t)N_NODES * NF];
__device__ float g_h2[(size_t)N_NODES * NF];
__device__ int   g_src[N_EDGES];
__device__ int   g_dst[N_EDGES];
__device__ int   g_csr[N_EDGES];
__device__ int   g_indeg[N_NODES];
__device__ int   g_outdeg[N_NODES];
__device__ int   g_rowtmp[N_NODES];
__device__ int   g_rowptr[N_NODES + 1];
__device__ int   g_cursor[N_NODES];
__device__ int   g_bsum[256];
__device__ double g_red[1];
__device__ int   g_is64[1];

// ---------------- edge dtype detection (parallel) ----------------
// int64 layout => every odd 32-bit word is the (zero) high half of a small id.
__global__ void detect_kernel(const unsigned int* __restrict__ w, int* __restrict__ flag) {
    __shared__ unsigned int sh[64];
    int t = threadIdx.x;
    unsigned int idx = 2u * (unsigned int)(t * 24999 + 13) + 1u;   // < 3.2M words
    sh[t] = w[idx];
    __syncthreads();
    if (t == 0) {
        unsigned int acc = 0;
        #pragma unroll
        for (int i = 0; i < 64; i++) acc |= sh[i];
        *flag = (acc == 0u) ? 1 : 0;
    }
}

__global__ void zero_misc_kernel(int* __restrict__ indeg, int* __restrict__ outdeg,
                                 double* __restrict__ red) {
    int i = blockIdx.x * blockDim.x + threadIdx.x;
    if (i < N_NODES) { indeg[i] = 0; outdeg[i] = 0; }
    if (i == 0) red[0] = 0.0;
}

// normalize edges to int32 + degree histograms
__global__ void prep_kernel(const void* __restrict__ ei, int* __restrict__ esrc,
                            int* __restrict__ edst, int* __restrict__ indeg,
                            int* __restrict__ outdeg, const int* __restrict__ flag) {
    int e = blockIdx.x * blockDim.x + threadIdx.x;
    if (e >= N_EDGES) return;
    int s, d;
    if (*flag) {
        const long long* p = (const long long*)ei;
        s = (int)p[e];
        d = (int)p[N_EDGES + e];
    } else {
        const int* p = (const int*)ei;
        s = p[e];
        d = p[N_EDGES + e];
    }
    esrc[e] = s;
    edst[e] = d;
    atomicAdd(indeg + d, 1);
    atomicAdd(outdeg + s, 1);
}

// ---------------- exclusive scan of indeg -> rowptr (3 kernels) ----------------
__global__ void scan1_kernel(const int* __restrict__ indeg, int* __restrict__ rowtmp,
                             int* __restrict__ bsum) {
    __shared__ int sh[512];
    int tid = threadIdx.x;
    int i = blockIdx.x * 512 + tid;
    sh[tid] = (i < N_NODES) ? indeg[i] : 0;
    __syncthreads();
    #pragma unroll
    for (int off = 1; off < 512; off <<= 1) {
        int t = (tid >= off) ? sh[tid - off] : 0;
        __syncthreads();
        sh[tid] += t;
        __syncthreads();
    }
    if (i < N_NODES) rowtmp[i] = sh[tid];     // inclusive within block
    if (tid == 511) bsum[blockIdx.x] = sh[511];
}

__global__ void scan2_kernel(int* __restrict__ bsum, int nb) {
    __shared__ int sh[256];
    int tid = threadIdx.x;
    sh[tid] = (tid < nb) ? bsum[tid] : 0;
    __syncthreads();
    #pragma unroll
    for (int off = 1; off < 256; off <<= 1) {
        int t = (tid >= off) ? sh[tid - off] : 0;
        __syncthreads();
        sh[tid] += t;
        __syncthreads();
    }
    if (tid < nb) bsum[tid] = sh[tid];        // inclusive
}

__global__ void scan3_kernel(const int* __restrict__ rowtmp, const int* __restrict__ bsum,
                             const int* __restrict__ indeg, int* __restrict__ rowptr,
                             int* __restrict__ cursor) {
    int i = blockIdx.x * blockDim.x + threadIdx.x;
    if (i >= N_NODES) return;
    int b = i >> 9;
    int add = (b > 0) ? bsum[b - 1] : 0;
    int inc = rowtmp[i] + add;
    rowptr[i + 1] = inc;
    cursor[i] = inc - indeg[i];
    if (i == 0) rowptr[0] = 0;
}

__global__ void fill_kernel(const int* __restrict__ esrc, const int* __restrict__ edst,
                            int* __restrict__ cursor, int* __restrict__ csr) {
    int e = blockIdx.x * blockDim.x + threadIdx.x;
    if (e >= N_EDGES) return;
    int pos = atomicAdd(cursor + edst[e], 1);
    csr[pos] = esrc[e];
}

// ---------------- aggregation: aggr[i] = sum_{j in N(i)} feat[j], gather-only ----------
// one warp per node; lane handles feats (2l, 2l+1); unroll-4 for MLP.
__global__ void __launch_bounds__(256) aggr_kernel(const float* __restrict__ feat,
                                                   float* __restrict__ aggr,
                                                   const int* __restrict__ rowptr,
                                                   const int* __restrict__ csr) {
    const int lane = threadIdx.x & 31;
    const int node = blockIdx.x * 8 + (threadIdx.x >> 5);
    if (node >= N_NODES) return;
    const int beg = rowptr[node];
    const int end = rowptr[node + 1];
    const float2* f2 = (const float2*)feat;

    float2 a0 = make_float2(0.f, 0.f), a1 = make_float2(0.f, 0.f);
    float2 a2 = make_float2(0.f, 0.f), a3 = make_float2(0.f, 0.f);
    int j = beg;
    for (; j + 4 <= end; j += 4) {
        int s0 = __ldg(csr + j + 0);
        int s1 = __ldg(csr + j + 1);
        int s2 = __ldg(csr + j + 2);
        int s3 = __ldg(csr + j + 3);
        float2 v0 = f2[(size_t)s0 * 32 + lane];
        float2 v1 = f2[(size_t)s1 * 32 + lane];
        float2 v2 = f2[(size_t)s2 * 32 + lane];
        float2 v3 = f2[(size_t)s3 * 32 + lane];
        a0.x += v0.x; a0.y += v0.y;
        a1.x += v1.x; a1.y += v1.y;
        a2.x += v2.x; a2.y += v2.y;
        a3.x += v3.x; a3.y += v3.y;
    }
    for (; j < end; j++) {
        int s = __ldg(csr + j);
        float2 v = f2[(size_t)s * 32 + lane];
        a0.x += v.x; a0.y += v.y;
    }
    float2 o;
    o.x = (a0.x + a1.x) + (a2.x + a3.x);
    o.y = (a0.y + a1.y) + (a2.y + a3.y);
    ((float2*)aggr)[(size_t)node * 32 + lane] = o;
}

// ---------------- fused GEMM: out = act( [A1|A2] @ [W1;W2] + b ) ---------------------
// [N x 128] @ [128 x 64]. Block: 256 rows x 64 cols, 256 threads, 8x8 per thread,
// packed fma.rn.f32x2 (2 MACs / instr).
__global__ void __launch_bounds__(256) fused_gemm_kernel(
    const float* __restrict__ A1, const float* __restrict__ A2,
    const float* __restrict__ W1, const float* __restrict__ W2,
    const float* __restrict__ bias, float* __restrict__ out,
    int n, int do_relu) {
    __shared__ float Ash[16][260];   // [k][row], pitch 260 floats (1040B, 16B-aligned)
    __shared__ float Wsh[16][64];    // [k][col]
    __shared__ float bsh[64];

    const int tid = threadIdx.x;
    const int tx = tid & 7;          // col group: cols tx*8 .. +7
    const int ty = tid >> 3;         // row group 0..31: rows ty*8 .. +7
    const int row_base = blockIdx.x * 256;

    if (tid < 64) bsh[tid] = bias[tid];

    unsigned long long acc[8][4];    // acc[i][p] = (out[i][2p], out[i][2p+1]) packed f32x2
    #pragma unroll
    for (int i = 0; i < 8; i++)
        #pragma unroll
        for (int p = 0; p < 4; p++) acc[i][p] = 0ull;

    int arow = row_base + tid;
    if (arow >= n) arow = n - 1;

    #pragma unroll 1
    for (int ch = 0; ch < 8; ch++) {
        const float* A = (ch < 4) ? A1 : A2;
        const float* W = (ch < 4) ? W1 : W2;
        const int k0 = (ch & 3) * 16;

        // global loads for this chunk
        float4 av[4];
        #pragma unroll
        for (int q = 0; q < 4; q++)
            av[q] = *reinterpret_cast<const float4*>(A + (size_t)arow * NF + k0 + q * 4);
        float4 wv = *reinterpret_cast<const float4*>(
            W + (size_t)(k0 + (tid >> 4)) * NF + (tid & 15) * 4);

        __syncthreads();
        #pragma unroll
        for (int q = 0; q < 4; q++) {
            Ash[q * 4 + 0][tid] = av[q].x;
            Ash[q * 4 + 1][tid] = av[q].y;
            Ash[q * 4 + 2][tid] = av[q].z;
            Ash[q * 4 + 3][tid] = av[q].w;
        }
        *reinterpret_cast<float4*>(&Wsh[tid >> 4][(tid & 15) * 4]) = wv;
        __syncthreads();

        #pragma unroll
        for (int kk = 0; kk < 16; kk++) {
            float4 aA = *reinterpret_cast<const float4*>(&Ash[kk][ty * 8]);
            float4 aB = *reinterpret_cast<const float4*>(&Ash[kk][ty * 8 + 4]);
            ulonglong2 wA = *reinterpret_cast<const ulonglong2*>(&Wsh[kk][tx * 8]);
            ulonglong2 wB = *reinterpret_cast<const ulonglong2*>(&Wsh[kk][tx * 8 + 4]);
            unsigned long long wp0 = wA.x, wp1 = wA.y, wp2 = wB.x, wp3 = wB.y;
            float ar[8] = {aA.x, aA.y, aA.z, aA.w, aB.x, aB.y, aB.z, aB.w};
            #pragma unroll
            for (int i = 0; i < 8; i++) {
                unsigned long long ad;
                asm("mov.b64 %0, {%1, %1};" : "=l"(ad) : "f"(ar[i]));
                asm("fma.rn.f32x2 %0, %1, %2, %0;" : "+l"(acc[i][0]) : "l"(ad), "l"(wp0));
                asm("fma.rn.f32x2 %0, %1, %2, %0;" : "+l"(acc[i][1]) : "l"(ad), "l"(wp1));
                asm("fma.rn.f32x2 %0, %1, %2, %0;" : "+l"(acc[i][2]) : "l"(ad), "l"(wp2));
                asm("fma.rn.f32x2 %0, %1, %2, %0;" : "+l"(acc[i][3]) : "l"(ad), "l"(wp3));
            }
        }
    }

    const int col = tx * 8;
    #pragma unroll
    for (int i = 0; i < 8; i++) {
        int r = row_base + ty * 8 + i;
        if (r < n) {
            float o[8];
            #pragma unroll
            for (int p = 0; p < 4; p++)
                asm("mov.b64 {%0, %1}, %2;" : "=f"(o[2 * p]), "=f"(o[2 * p + 1])
                                            : "l"(acc[i][p]));
            #pragma unroll
            for (int c = 0; c < 8; c++) {
                o[c] += bsh[col + c];
                if (do_relu) o[c] = fmaxf(o[c], 0.f);
            }
            float4* dst = reinterpret_cast<float4*>(out + (size_t)r * NF + col);
            dst[0] = make_float4(o[0], o[1], o[2], o[3]);
            dst[1] = make_float4(o[4], o[5], o[6], o[7]);
        }
    }
}

// ---------------- layer 3 collapsed: sum_i outdeg[i]*(h2_i.wrel3) + (h2_i.wroot3) -----
__global__ void __launch_bounds__(256) final_kernel(const float* __restrict__ h2,
                                                    const int* __restrict__ deg,
                                                    const float* __restrict__ wrel3,
                                                    const float* __restrict__ wroot3,
                                                    double* __restrict__ red) {
    const int lane = threadIdx.x & 31;
    const int warp = threadIdx.x >> 5;
    const int gw = blockIdx.x * 8 + warp;
    const float2 wr = ((const float2*)wrel3)[lane];
    const float2 wo = ((const float2*)wroot3)[lane];

    float lv = 0.f;
    int i0 = gw * 16;
    int i1 = i0 + 16; if (i1 > N_NODES) i1 = N_NODES;
    for (int i = i0; i < i1; i++) {
        float2 a = ((const float2*)h2)[(size_t)i * 32 + lane];
        float pv = a.x * wr.x + a.y * wr.y;
        float pu = a.x * wo.x + a.y * wo.y;
        lv += (float)__ldg(deg + i) * pv + pu;
    }
    #pragma unroll
    for (int off = 16; off; off >>= 1) lv += __shfl_xor_sync(0xffffffffu, lv, off);

    __shared__ double sh[8];
    if (lane == 0) sh[warp] = (double)lv;
    __syncthreads();
    if (threadIdx.x == 0) {
        double s = 0.0;
        #pragma unroll
        for (int w = 0; w < 8; w++) s += sh[w];
        atomicAdd(red, s);
    }
}

__global__ void write_out_kernel(float* __restrict__ out, const double* __restrict__ red,
                                 const float* __restrict__ b3) {
    if (threadIdx.x == 0 && blockIdx.x == 0)
        out[0] = (float)(red[0] / (double)N_NODES + (double)b3[0]);
}

// ---------------- launch ----------------
extern "C" void kernel_launch(void* const* d_in, const int* in_sizes, int n_in,
                              void* d_out, int out_size) {
    const float* x      = (const float*)d_in[0];
    const void*  ei     = d_in[1];
    const float* wrel1  = (const float*)d_in[2];
    const float* brel1  = (const float*)d_in[3];
    const float* wroot1 = (const float*)d_in[4];
    const float* wrel2  = (const float*)d_in[5];
    const float* brel2  = (const float*)d_in[6];
    const float* wroot2 = (const float*)d_in[7];
    const float* wrel3  = (const float*)d_in[8];
    const float* brel3  = (const float*)d_in[9];
    const float* wroot3 = (const float*)d_in[10];
    float* out = (float*)d_out;

    float *aggr, *h1, *h2;
    int *esrc, *edst, *csr, *indeg, *outdeg, *rowtmp, *rowptr, *cursor, *bsum, *is64;
    double* red;
    cudaGetSymbolAddress((void**)&aggr,   g_aggr);
    cudaGetSymbolAddress((void**)&h1,     g_h1);
    cudaGetSymbolAddress((void**)&h2,     g_h2);
    cudaGetSymbolAddress((void**)&esrc,   g_src);
    cudaGetSymbolAddress((void**)&edst,   g_dst);
    cudaGetSymbolAddress((void**)&csr,    g_csr);
    cudaGetSymbolAddress((void**)&indeg,  g_indeg);
    cudaGetSymbolAddress((void**)&outdeg, g_outdeg);
    cudaGetSymbolAddress((void**)&rowtmp, g_rowtmp);
    cudaGetSymbolAddress((void**)&rowptr, g_rowptr);
    cudaGetSymbolAddress((void**)&cursor, g_cursor);
    cudaGetSymbolAddress((void**)&bsum,   g_bsum);
    cudaGetSymbolAddress((void**)&red,    g_red);
    cudaGetSymbolAddress((void**)&is64,   g_is64);

    const int nblk   = (N_NODES + 255) / 256;     // 391
    const int eblk   = (N_EDGES + 255) / 256;     // 6250
    const int sblk   = (N_NODES + 511) / 512;     // 196
    const int ablk   = (N_NODES + 7) / 8;         // 12500
    const int gblk   = (N_NODES + 255) / 256;     // 391
    const int fblk   = (N_NODES + 127) / 128;     // 782

    // prep + CSR build
    detect_kernel<<<1, 64>>>((const unsigned int*)ei, is64);
    zero_misc_kernel<<<nblk, 256>>>(indeg, outdeg, red);
    prep_kernel<<<eblk, 256>>>(ei, esrc, edst, indeg, outdeg, is64);
    scan1_kernel<<<sblk, 512>>>(indeg, rowtmp, bsum);
    scan2_kernel<<<1, 256>>>(bsum, sblk);
    scan3_kernel<<<nblk, 256>>>(rowtmp, bsum, indeg, rowptr, cursor);
    fill_kernel<<<eblk, 256>>>(esrc, edst, cursor, csr);

    // layer 1
    aggr_kernel<<<ablk, 256>>>(x, aggr, rowptr, csr);
    fused_gemm_kernel<<<gblk, 256>>>(aggr, x, wrel1, wroot1, brel1, h1, N_NODES, 1);

    // layer 2
    aggr_kernel<<<ablk, 256>>>(h1, aggr, rowptr, csr);
    fused_gemm_kernel<<<gblk, 256>>>(aggr, h1, wrel2, wroot2, brel2, h2, N_NODES, 1);

    // layer 3 collapsed into a degree-weighted reduction
    final_kernel<<<fblk, 256>>>(h2, outdeg, wrel3, wroot3, red);
    write_out_kernel<<<1, 32>>>(out, red, brel3);
}

// round 3
// speedup vs baseline: 1.4889x; 1.1106x over previous
#include <cuda_runtime.h>
#include <cuda_bf16.h>
#include <cstdint>

#define N_NODES 100000
#define N_EDGES 1600000
#define NF 64

// ---------------- scratch (static __device__ — no allocations allowed) ----------------
__device__ __nv_bfloat162 g_xbf [(size_t)N_NODES * 32];
__device__ __nv_bfloat162 g_aggr[(size_t)N_NODES * 32];
__device__ __nv_bfloat162 g_h1  [(size_t)N_NODES * 32];
__device__ __nv_bfloat162 g_h2  [(size_t)N_NODES * 32];
__device__ int   g_csr[N_EDGES];
__device__ int   g_indeg[N_NODES];
__device__ int   g_outdeg[N_NODES];
__device__ int   g_rowtmp[N_NODES];
__device__ int   g_rowptr[N_NODES + 1];
__device__ int   g_cursor[N_NODES];
__device__ int   g_bsum[256];
__device__ double g_red[1];
__device__ int   g_is64[1];

// ---------------- edge dtype detection (parallel) ----------------
// int64 layout => every odd 32-bit word is the (zero) high half of a small id.
__global__ void detect_kernel(const unsigned int* __restrict__ w, int* __restrict__ flag) {
    __shared__ unsigned int sh[64];
    int t = threadIdx.x;
    unsigned int idx = 2u * (unsigned int)(t * 24999 + 13) + 1u;   // < 3.2M words
    sh[t] = w[idx];
    __syncthreads();
    if (t == 0) {
        unsigned int acc = 0;
        #pragma unroll
        for (int i = 0; i < 64; i++) acc |= sh[i];
        *flag = (acc == 0u) ? 1 : 0;
    }
}

__global__ void zero_misc_kernel(int* __restrict__ indeg, int* __restrict__ outdeg,
                                 double* __restrict__ red) {
    int i = blockIdx.x * blockDim.x + threadIdx.x;
    if (i < N_NODES) { indeg[i] = 0; outdeg[i] = 0; }
    if (i == 0) red[0] = 0.0;
}

// degree histograms straight off edge_index (no normalized copy)
__global__ void hist_kernel(const void* __restrict__ ei, int* __restrict__ indeg,
                            int* __restrict__ outdeg, const int* __restrict__ flag) {
    int e = blockIdx.x * blockDim.x + threadIdx.x;
    if (e >= N_EDGES) return;
    int s, d;
    if (*flag) {
        const long long* p = (const long long*)ei;
        s = (int)p[e];
        d = (int)p[N_EDGES + e];
    } else {
        const int* p = (const int*)ei;
        s = p[e];
        d = p[N_EDGES + e];
    }
    atomicAdd(indeg + d, 1);
    atomicAdd(outdeg + s, 1);
}

// ---------------- exclusive scan of indeg -> rowptr (3 kernels) ----------------
__global__ void scan1_kernel(const int* __restrict__ indeg, int* __restrict__ rowtmp,
                             int* __restrict__ bsum) {
    __shared__ int sh[512];
    int tid = threadIdx.x;
    int i = blockIdx.x * 512 + tid;
    sh[tid] = (i < N_NODES) ? indeg[i] : 0;
    __syncthreads();
    #pragma unroll
    for (int off = 1; off < 512; off <<= 1) {
        int t = (tid >= off) ? sh[tid - off] : 0;
        __syncthreads();
        sh[tid] += t;
        __syncthreads();
    }
    if (i < N_NODES) rowtmp[i] = sh[tid];     // inclusive within block
    if (tid == 511) bsum[blockIdx.x] = sh[511];
}

__global__ void scan2_kernel(int* __restrict__ bsum, int nb) {
    __shared__ int sh[256];
    int tid = threadIdx.x;
    sh[tid] = (tid < nb) ? bsum[tid] : 0;
    __syncthreads();
    #pragma unroll
    for (int off = 1; off < 256; off <<= 1) {
        int t = (tid >= off) ? sh[tid - off] : 0;
        __syncthreads();
        sh[tid] += t;
        __syncthreads();
    }
    if (tid < nb) bsum[tid] = sh[tid];        // inclusive
}

__global__ void scan3_kernel(const int* __restrict__ rowtmp, const int* __restrict__ bsum,
                             const int* __restrict__ indeg, int* __restrict__ rowptr,
                             int* __restrict__ cursor) {
    int i = blockIdx.x * blockDim.x + threadIdx.x;
    if (i >= N_NODES) return;
    int b = i >> 9;
    int add = (b > 0) ? bsum[b - 1] : 0;
    int inc = rowtmp[i] + add;
    rowptr[i + 1] = inc;
    cursor[i] = inc - indeg[i];
    if (i == 0) rowptr[0] = 0;
}

__global__ void fill_kernel(const void* __restrict__ ei, int* __restrict__ cursor,
                            int* __restrict__ csr, const int* __restrict__ flag) {
    int e = blockIdx.x * blockDim.x + threadIdx.x;
    if (e >= N_EDGES) return;
    int s, d;
    if (*flag) {
        const long long* p = (const long long*)ei;
        s = (int)p[e];
        d = (int)p[N_EDGES + e];
    } else {
        const int* p = (const int*)ei;
        s = p[e];
        d = p[N_EDGES + e];
    }
    int pos = atomicAdd(cursor + d, 1);
    csr[pos] = s;
}

// ---------------- x (f32) -> bf16 ----------------
__global__ void convert_kernel(const float* __restrict__ x, __nv_bfloat162* __restrict__ xbf) {
    int i = blockIdx.x * blockDim.x + threadIdx.x;       // one float4 -> 2 bf162
    if (i >= (N_NODES * NF) / 4) return;
    float4 v = reinterpret_cast<const float4*>(x)[i];
    __nv_bfloat162 a = __float22bfloat162_rn(make_float2(v.x, v.y));
    __nv_bfloat162 b = __float22bfloat162_rn(make_float2(v.z, v.w));
    xbf[2 * i]     = a;
    xbf[2 * i + 1] = b;
}

// ---------------- aggregation: aggr[i] = sum_{j in N(i)} feat[j] (bf16 in/out) --------
// one warp per node; lane handles one bf16x2 (2 cols); unroll-4 for MLP.
__global__ void __launch_bounds__(256) aggr_kernel(const __nv_bfloat162* __restrict__ feat,
                                                   __nv_bfloat162* __restrict__ aggr,
                                                   const int* __restrict__ rowptr,
                                                   const int* __restrict__ csr) {
    const int lane = threadIdx.x & 31;
    const int node = blockIdx.x * 8 + (threadIdx.x >> 5);
    if (node >= N_NODES) return;
    const int beg = rowptr[node];
    const int end = rowptr[node + 1];

    float2 a0 = make_float2(0.f, 0.f), a1 = make_float2(0.f, 0.f);
    float2 a2 = make_float2(0.f, 0.f), a3 = make_float2(0.f, 0.f);
    int j = beg;
    for (; j + 4 <= end; j += 4) {
        int s0 = __ldg(csr + j + 0);
        int s1 = __ldg(csr + j + 1);
        int s2 = __ldg(csr + j + 2);
        int s3 = __ldg(csr + j + 3);
        float2 v0 = __bfloat1622float2(feat[(size_t)s0 * 32 + lane]);
        float2 v1 = __bfloat1622float2(feat[(size_t)s1 * 32 + lane]);
        float2 v2 = __bfloat1622float2(feat[(size_t)s2 * 32 + lane]);
        float2 v3 = __bfloat1622float2(feat[(size_t)s3 * 32 + lane]);
        a0.x += v0.x; a0.y += v0.y;
        a1.x += v1.x; a1.y += v1.y;
        a2.x += v2.x; a2.y += v2.y;
        a3.x += v3.x; a3.y += v3.y;
    }
    for (; j < end; j++) {
        int s = __ldg(csr + j);
        float2 v = __bfloat1622float2(feat[(size_t)s * 32 + lane]);
        a0.x += v.x; a0.y += v.y;
    }
    float2 o;
    o.x = (a0.x + a1.x) + (a2.x + a3.x);
    o.y = (a0.y + a1.y) + (a2.y + a3.y);
    aggr[(size_t)node * 32 + lane] = __float22bfloat162_rn(o);
}

// ---------------- fused GEMM: out = act( [A1|A2] @ [W1;W2] + b ), A bf16 -------------
// [N x 128] @ [128 x 64]. Block: 256 rows x 64 cols, 256 threads, 8x8 per thread,
// packed fma.rn.f32x2 inner loop (2 MACs / instr), f32 accumulation, bf16 output.
__global__ void __launch_bounds__(256) fused_gemm_kernel(
    const __nv_bfloat162* __restrict__ A1, const __nv_bfloat162* __restrict__ A2,
    const float* __restrict__ W1, const float* __restrict__ W2,
    const float* __restrict__ bias, __nv_bfloat162* __restrict__ out,
    int n, int do_relu) {
    __shared__ float Ash[16][260];   // [k][row], pitch 260 floats
    __shared__ float Wsh[16][64];    // [k][col]
    __shared__ float bsh[64];

    const int tid = threadIdx.x;
    const int tx = tid & 7;          // col group: cols tx*8 .. +7
    const int ty = tid >> 3;         // row group 0..31: rows ty*8 .. +7
    const int row_base = blockIdx.x * 256;

    if (tid < 64) bsh[tid] = bias[tid];

    unsigned long long acc[8][4];    // acc[i][p] = (out[i][2p], out[i][2p+1]) packed f32x2
    #pragma unroll
    for (int i = 0; i < 8; i++)
        #pragma unroll
        for (int p = 0; p < 4; p++) acc[i][p] = 0ull;

    int arow = row_base + tid;
    if (arow >= n) arow = n - 1;

    #pragma unroll 1
    for (int ch = 0; ch < 8; ch++) {
        const __nv_bfloat162* A = (ch < 4) ? A1 : A2;
        const float* W = (ch < 4) ? W1 : W2;
        const int k0 = (ch & 3) * 16;          // k offset within the 64-wide half

        // global loads: 16 bf16 k-values = 8 bf162 = 2 x 16B
        const __nv_bfloat162* abase = A + (size_t)arow * 32 + (k0 >> 1);
        uint4 ua = *reinterpret_cast<const uint4*>(abase);
        uint4 ub = *reinterpret_cast<const uint4*>(abase + 4);
        float4 wv = *reinterpret_cast<const float4*>(
            W + (size_t)(k0 + (tid >> 4)) * NF + (tid & 15) * 4);

        float2 f[8];
        f[0] = __bfloat1622float2(*reinterpret_cast<__nv_bfloat162*>(&ua.x));
        f[1] = __bfloat1622float2(*reinterpret_cast<__nv_bfloat162*>(&ua.y));
        f[2] = __bfloat1622float2(*reinterpret_cast<__nv_bfloat162*>(&ua.z));
        f[3] = __bfloat1622float2(*reinterpret_cast<__nv_bfloat162*>(&ua.w));
        f[4] = __bfloat1622float2(*reinterpret_cast<__nv_bfloat162*>(&ub.x));
        f[5] = __bfloat1622float2(*reinterpret_cast<__nv_bfloat162*>(&ub.y));
        f[6] = __bfloat1622float2(*reinterpret_cast<__nv_bfloat162*>(&ub.z));
        f[7] = __bfloat1622float2(*reinterpret_cast<__nv_bfloat162*>(&ub.w));

        __syncthreads();
        #pragma unroll
        for (int q = 0; q < 8; q++) {
            Ash[2 * q + 0][tid] = f[q].x;
            Ash[2 * q + 1][tid] = f[q].y;
        }
        *reinterpret_cast<float4*>(&Wsh[tid >> 4][(tid & 15) * 4]) = wv;
        __syncthreads();

        #pragma unroll
        for (int kk = 0; kk < 16; kk++) {
            float4 aA = *reinterpret_cast<const float4*>(&Ash[kk][ty * 8]);
            float4 aB = *reinterpret_cast<const float4*>(&Ash[kk][ty * 8 + 4]);
            ulonglong2 wA = *reinterpret_cast<const ulonglong2*>(&Wsh[kk][tx * 8]);
            ulonglong2 wB = *reinterpret_cast<const ulonglong2*>(&Wsh[kk][tx * 8 + 4]);
            unsigned long long wp0 = wA.x, wp1 = wA.y, wp2 = wB.x, wp3 = wB.y;
            float ar[8] = {aA.x, aA.y, aA.z, aA.w, aB.x, aB.y, aB.z, aB.w};
            #pragma unroll
            for (int i = 0; i < 8; i++) {
                unsigned long long ad;
                asm("mov.b64 %0, {%1, %1};" : "=l"(ad) : "f"(ar[i]));
                asm("fma.rn.f32x2 %0, %1, %2, %0;" : "+l"(acc[i][0]) : "l"(ad), "l"(wp0));
                asm("fma.rn.f32x2 %0, %1, %2, %0;" : "+l"(acc[i][1]) : "l"(ad), "l"(wp1));
                asm("fma.rn.f32x2 %0, %1, %2, %0;" : "+l"(acc[i][2]) : "l"(ad), "l"(wp2));
                asm("fma.rn.f32x2 %0, %1, %2, %0;" : "+l"(acc[i][3]) : "l"(ad), "l"(wp3));
            }
        }
    }

    const int col = tx * 8;
    #pragma unroll
    for (int i = 0; i < 8; i++) {
        int r = row_base + ty * 8 + i;
        if (r < n) {
            float o[8];
            #pragma unroll
            for (int p = 0; p < 4; p++)
                asm("mov.b64 {%0, %1}, %2;" : "=f"(o[2 * p]), "=f"(o[2 * p + 1])
                                            : "l"(acc[i][p]));
            #pragma unroll
            for (int c = 0; c < 8; c++) {
                o[c] += bsh[col + c];
                if (do_relu) o[c] = fmaxf(o[c], 0.f);
            }
            __nv_bfloat162 ob[4];
            #pragma unroll
            for (int p = 0; p < 4; p++)
                ob[p] = __float22bfloat162_rn(make_float2(o[2 * p], o[2 * p + 1]));
            *reinterpret_cast<uint4*>(out + (size_t)r * 32 + (col >> 1)) =
                *reinterpret_cast<uint4*>(ob);
        }
    }
}

// ---------------- layer 3 collapsed: sum_i outdeg[i]*(h2_i.wrel3) + (h2_i.wroot3) -----
__global__ void __launch_bounds__(256) final_kernel(const __nv_bfloat162* __restrict__ h2,
                                                    const int* __restrict__ deg,
                                                    const float* __restrict__ wrel3,
                                                    const float* __restrict__ wroot3,
                                                    double* __restrict__ red) {
    const int lane = threadIdx.x & 31;
    const int warp = threadIdx.x >> 5;
    const int gw = blockIdx.x * 8 + warp;
    const float2 wr = ((const float2*)wrel3)[lane];
    const float2 wo = ((const float2*)wroot3)[lane];

    float lv = 0.f;
    int i0 = gw * 16;
    int i1 = i0 + 16; if (i1 > N_NODES) i1 = N_NODES;
    for (int i = i0; i < i1; i++) {
        float2 a = __bfloat1622float2(h2[(size_t)i * 32 + lane]);
        float pv = a.x * wr.x + a.y * wr.y;
        float pu = a.x * wo.x + a.y * wo.y;
        lv += (float)__ldg(deg + i) * pv + pu;
    }
    #pragma unroll
    for (int off = 16; off; off >>= 1) lv += __shfl_xor_sync(0xffffffffu, lv, off);

    __shared__ double sh[8];
    if (lane == 0) sh[warp] = (double)lv;
    __syncthreads();
    if (threadIdx.x == 0) {
        double s = 0.0;
        #pragma unroll
        for (int w = 0; w < 8; w++) s += sh[w];
        atomicAdd(red, s);
    }
}

__global__ void write_out_kernel(float* __restrict__ out, const double* __restrict__ red,
                                 const float* __restrict__ b3) {
    if (threadIdx.x == 0 && blockIdx.x == 0)
        out[0] = (float)(red[0] / (double)N_NODES + (double)b3[0]);
}

// ---------------- launch ----------------
extern "C" void kernel_launch(void* const* d_in, const int* in_sizes, int n_in,
                              void* d_out, int out_size) {
    const float* x      = (const float*)d_in[0];
    const void*  ei     = d_in[1];
    const float* wrel1  = (const float*)d_in[2];
    const float* brel1  = (const float*)d_in[3];
    const float* wroot1 = (const float*)d_in[4];
    const float* wrel2  = (const float*)d_in[5];
    const float* brel2  = (const float*)d_in[6];
    const float* wroot2 = (const float*)d_in[7];
    const float* wrel3  = (const float*)d_in[8];
    const float* brel3  = (const float*)d_in[9];
    const float* wroot3 = (const float*)d_in[10];
    float* out = (float*)d_out;

    __nv_bfloat162 *xbf, *aggr, *h1, *h2;
    int *csr, *indeg, *outdeg, *rowtmp, *rowptr, *cursor, *bsum, *is64;
    double* red;
    cudaGetSymbolAddress((void**)&xbf,    g_xbf);
    cudaGetSymbolAddress((void**)&aggr,   g_aggr);
    cudaGetSymbolAddress((void**)&h1,     g_h1);
    cudaGetSymbolAddress((void**)&h2,     g_h2);
    cudaGetSymbolAddress((void**)&csr,    g_csr);
    cudaGetSymbolAddress((void**)&indeg,  g_indeg);
    cudaGetSymbolAddress((void**)&outdeg, g_outdeg);
    cudaGetSymbolAddress((void**)&rowtmp, g_rowtmp);
    cudaGetSymbolAddress((void**)&rowptr, g_rowptr);
    cudaGetSymbolAddress((void**)&cursor, g_cursor);
    cudaGetSymbolAddress((void**)&bsum,   g_bsum);
    cudaGetSymbolAddress((void**)&red,    g_red);
    cudaGetSymbolAddress((void**)&is64,   g_is64);

    const int nblk = (N_NODES + 255) / 256;     // 391
    const int eblk = (N_EDGES + 255) / 256;     // 6250
    const int sblk = (N_NODES + 511) / 512;     // 196
    const int ablk = (N_NODES + 7) / 8;         // 12500
    const int cblk = ((N_NODES * NF) / 4 + 255) / 256;
    const int fblk = (N_NODES + 127) / 128;     // 782

    // prep + CSR build
    detect_kernel<<<1, 64>>>((const unsigned int*)ei, is64);
    zero_misc_kernel<<<nblk, 256>>>(indeg, outdeg, red);
    hist_kernel<<<eblk, 256>>>(ei, indeg, outdeg, is64);
    convert_kernel<<<cblk, 256>>>(x, xbf);
    scan1_kernel<<<sblk, 512>>>(indeg, rowtmp, bsum);
    scan2_kernel<<<1, 256>>>(bsum, sblk);
    scan3_kernel<<<nblk, 256>>>(rowtmp, bsum, indeg, rowptr, cursor);
    fill_kernel<<<eblk, 256>>>(ei, cursor, csr, is64);

    // layer 1
    aggr_kernel<<<ablk, 256>>>(xbf, aggr, rowptr, csr);
    fused_gemm_kernel<<<nblk, 256>>>(aggr, xbf, wrel1, wroot1, brel1, h1, N_NODES, 1);

    // layer 2
    aggr_kernel<<<ablk, 256>>>(h1, aggr, rowptr, csr);
    fused_gemm_kernel<<<nblk, 256>>>(aggr, h1, wrel2, wroot2, brel2, h2, N_NODES, 1);

    // layer 3 collapsed into a degree-weighted reduction
    final_kernel<<<fblk, 256>>>(h2, outdeg, wrel3, wroot3, red);
    write_out_kernel<<<1, 32>>>(out, red, brel3);
}

// round 4
// speedup vs baseline: 2.0174x; 1.3549x over previous
#include <cuda_runtime.h>
#include <cuda_bf16.h>
#include <cstdint>

#define N_NODES 100000
#define N_EDGES 1600000
#define NF 64

// ---------------- scratch (static __device__ — no allocations allowed) ----------------
__device__ __nv_bfloat162 g_xbf [(size_t)N_NODES * 32];
__device__ __nv_bfloat162 g_aggr[(size_t)N_NODES * 32];
__device__ __nv_bfloat162 g_h1  [(size_t)N_NODES * 32];
__device__ __nv_bfloat162 g_h2  [(size_t)N_NODES * 32];
__device__ __nv_bfloat16  g_whi [2 * 128 * 64];
__device__ __nv_bfloat16  g_wlo [2 * 128 * 64];
__device__ int   g_csr[N_EDGES];
__device__ int   g_indeg[N_NODES];
__device__ int   g_outdeg[N_NODES];
__device__ int   g_rowtmp[N_NODES];
__device__ int   g_rowptr[N_NODES + 1];
__device__ int   g_cursor[N_NODES];
__device__ int   g_bsum[256];
__device__ double g_red[1];
__device__ int   g_is64[1];

static __device__ __forceinline__ uint32_t su32(const void* p) {
    return (uint32_t)__cvta_generic_to_shared(p);
}

// ---------------- edge dtype detection (parallel) ----------------
__global__ void detect_kernel(const unsigned int* __restrict__ w, int* __restrict__ flag) {
    __shared__ unsigned int sh[64];
    int t = threadIdx.x;
    unsigned int idx = 2u * (unsigned int)(t * 24999 + 13) + 1u;   // < 3.2M words
    sh[t] = w[idx];
    __syncthreads();
    if (t == 0) {
        unsigned int acc = 0;
        #pragma unroll
        for (int i = 0; i < 64; i++) acc |= sh[i];
        *flag = (acc == 0u) ? 1 : 0;
    }
}

__global__ void zero_misc_kernel(int* __restrict__ indeg, int* __restrict__ outdeg,
                                 double* __restrict__ red) {
    int i = blockIdx.x * blockDim.x + threadIdx.x;
    if (i < N_NODES) { indeg[i] = 0; outdeg[i] = 0; }
    if (i == 0) red[0] = 0.0;
}

// ---------------- fused: degree histograms + x -> bf16 conversion ----------------
__global__ void __launch_bounds__(256) histconv_kernel(
    const void* __restrict__ ei, const float* __restrict__ x,
    __nv_bfloat162* __restrict__ xbf, int* __restrict__ indeg,
    int* __restrict__ outdeg, const int* __restrict__ flag) {
    int idx = blockIdx.x * 256 + threadIdx.x;
    if (idx < (N_NODES * NF) / 8) {          // one uint4 of bf16 out per thread
        const float4* xs = (const float4*)x;
        float4 v0 = xs[2 * idx], v1 = xs[2 * idx + 1];
        __align__(16) __nv_bfloat162 o[4];
        o[0] = __float22bfloat162_rn(make_float2(v0.x, v0.y));
        o[1] = __float22bfloat162_rn(make_float2(v0.z, v0.w));
        o[2] = __float22bfloat162_rn(make_float2(v1.x, v1.y));
        o[3] = __float22bfloat162_rn(make_float2(v1.z, v1.w));
        reinterpret_cast<uint4*>(xbf)[idx] = *reinterpret_cast<uint4*>(o);
    }
    if (idx < N_EDGES) {
        int s, d;
        if (*flag) {
            const long long* p = (const long long*)ei;
            s = (int)p[idx];
            d = (int)p[N_EDGES + idx];
        } else {
            const int* p = (const int*)ei;
            s = p[idx];
            d = p[N_EDGES + idx];
        }
        atomicAdd(indeg + d, 1);
        atomicAdd(outdeg + s, 1);
    }
}

// ---------------- weights -> bf16 hi/lo split ----------------
__global__ void wconv_kernel(const float* __restrict__ wrel1, const float* __restrict__ wroot1,
                             const float* __restrict__ wrel2, const float* __restrict__ wroot2,
                             __nv_bfloat16* __restrict__ whi, __nv_bfloat16* __restrict__ wlo) {
    int i = blockIdx.x * 256 + threadIdx.x;     // 0..16383
    if (i >= 2 * 128 * 64) return;
    int layer = i >> 13;
    int rem = i & 8191;
    int k = rem >> 6;
    int nn = rem & 63;
    const float* src = layer ? (k < 64 ? wrel2 : wroot2) : (k < 64 ? wrel1 : wroot1);
    float w = src[(k & 63) * 64 + nn];
    __nv_bfloat16 hi = __float2bfloat16(w);
    __nv_bfloat16 lo = __float2bfloat16(w - __bfloat162float(hi));
    whi[i] = hi;
    wlo[i] = lo;
}

// ---------------- exclusive scan of indeg -> rowptr (3 kernels) ----------------
__global__ void scan1_kernel(const int* __restrict__ indeg, int* __restrict__ rowtmp,
                             int* __restrict__ bsum) {
    __shared__ int sh[512];
    int tid = threadIdx.x;
    int i = blockIdx.x * 512 + tid;
    sh[tid] = (i < N_NODES) ? indeg[i] : 0;
    __syncthreads();
    #pragma unroll
    for (int off = 1; off < 512; off <<= 1) {
        int t = (tid >= off) ? sh[tid - off] : 0;
        __syncthreads();
        sh[tid] += t;
        __syncthreads();
    }
    if (i < N_NODES) rowtmp[i] = sh[tid];
    if (tid == 511) bsum[blockIdx.x] = sh[511];
}

__global__ void scan2_kernel(int* __restrict__ bsum, int nb) {
    __shared__ int sh[256];
    int tid = threadIdx.x;
    sh[tid] = (tid < nb) ? bsum[tid] : 0;
    __syncthreads();
    #pragma unroll
    for (int off = 1; off < 256; off <<= 1) {
        int t = (tid >= off) ? sh[tid - off] : 0;
        __syncthreads();
        sh[tid] += t;
        __syncthreads();
    }
    if (tid < nb) bsum[tid] = sh[tid];
}

__global__ void scan3_kernel(const int* __restrict__ rowtmp, const int* __restrict__ bsum,
                             const int* __restrict__ indeg, int* __restrict__ rowptr,
                             int* __restrict__ cursor) {
    int i = blockIdx.x * blockDim.x + threadIdx.x;
    if (i >= N_NODES) return;
    int b = i >> 9;
    int add = (b > 0) ? bsum[b - 1] : 0;
    int inc = rowtmp[i] + add;
    rowptr[i + 1] = inc;
    cursor[i] = inc - indeg[i];
    if (i == 0) rowptr[0] = 0;
}

__global__ void fill_kernel(const void* __restrict__ ei, int* __restrict__ cursor,
                            int* __restrict__ csr, const int* __restrict__ flag) {
    int e = blockIdx.x * blockDim.x + threadIdx.x;
    if (e >= N_EDGES) return;
    int s, d;
    if (*flag) {
        const long long* p = (const long long*)ei;
        s = (int)p[e];
        d = (int)p[N_EDGES + e];
    } else {
        const int* p = (const int*)ei;
        s = p[e];
        d = p[N_EDGES + e];
    }
    int pos = atomicAdd(cursor + d, 1);
    csr[pos] = s;
}

// ---------------- aggregation: aggr[i] = sum_{j in N(i)} feat[j] (bf16) --------------
// one warp per node; 4 edges per iteration; each 8-lane group loads a full
// 128B row via LDG.128; cross-group shfl reduce at the end.
__global__ void __launch_bounds__(256) aggr_kernel(const __nv_bfloat162* __restrict__ feat,
                                                   __nv_bfloat162* __restrict__ aggr,
                                                   const int* __restrict__ rowptr,
                                                   const int* __restrict__ csr) {
    const int lane = threadIdx.x & 31;
    const int grp = lane >> 3;
    const int sub = lane & 7;
    const int node = blockIdx.x * 8 + (threadIdx.x >> 5);
    if (node >= N_NODES) return;
    const int beg = rowptr[node];
    const int end = rowptr[node + 1];

    float2 acc[4];
    #pragma unroll
    for (int q = 0; q < 4; q++) acc[q] = make_float2(0.f, 0.f);

    for (int j = beg; j < end; j += 8) {
        int e0 = j + grp;
        int e1 = j + 4 + grp;
        if (e0 < end) {
            int s = __ldg(csr + e0);
            uint4 v = *reinterpret_cast<const uint4*>(feat + (size_t)s * 32 + sub * 4);
            acc[0] = make_float2(acc[0].x + __bfloat1622float2(*(__nv_bfloat162*)&v.x).x,
                                 acc[0].y + __bfloat1622float2(*(__nv_bfloat162*)&v.x).y);
            acc[1] = make_float2(acc[1].x + __bfloat1622float2(*(__nv_bfloat162*)&v.y).x,
                                 acc[1].y + __bfloat1622float2(*(__nv_bfloat162*)&v.y).y);
            acc[2] = make_float2(acc[2].x + __bfloat1622float2(*(__nv_bfloat162*)&v.z).x,
                                 acc[2].y + __bfloat1622float2(*(__nv_bfloat162*)&v.z).y);
            acc[3] = make_float2(acc[3].x + __bfloat1622float2(*(__nv_bfloat162*)&v.w).x,
                                 acc[3].y + __bfloat1622float2(*(__nv_bfloat162*)&v.w).y);
        }
        if (e1 < end) {
            int s = __ldg(csr + e1);
            uint4 v = *reinterpret_cast<const uint4*>(feat + (size_t)s * 32 + sub * 4);
            acc[0] = make_float2(acc[0].x + __bfloat1622float2(*(__nv_bfloat162*)&v.x).x,
                                 acc[0].y + __bfloat1622float2(*(__nv_bfloat162*)&v.x).y);
            acc[1] = make_float2(acc[1].x + __bfloat1622float2(*(__nv_bfloat162*)&v.y).x,
                                 acc[1].y + __bfloat1622float2(*(__nv_bfloat162*)&v.y).y);
            acc[2] = make_float2(acc[2].x + __bfloat1622float2(*(__nv_bfloat162*)&v.z).x,
                                 acc[2].y + __bfloat1622float2(*(__nv_bfloat162*)&v.z).y);
            acc[3] = make_float2(acc[3].x + __bfloat1622float2(*(__nv_bfloat162*)&v.w).x,
                                 acc[3].y + __bfloat1622float2(*(__nv_bfloat162*)&v.w).y);
        }
    }

    // reduce across the 4 groups (lanes differing in bits 3,4)
    #pragma unroll
    for (int q = 0; q < 4; q++) {
        acc[q].x += __shfl_xor_sync(0xffffffffu, acc[q].x, 8);
        acc[q].y += __shfl_xor_sync(0xffffffffu, acc[q].y, 8);
        acc[q].x += __shfl_xor_sync(0xffffffffu, acc[q].x, 16);
        acc[q].y += __shfl_xor_sync(0xffffffffu, acc[q].y, 16);
    }
    if (grp == 0) {
        __align__(16) __nv_bfloat162 ob[4];
        #pragma unroll
        for (int q = 0; q < 4; q++) ob[q] = __float22bfloat162_rn(acc[q]);
        *reinterpret_cast<uint4*>(aggr + (size_t)node * 32 + sub * 4) =
            *reinterpret_cast<uint4*>(ob);
    }
}

// ---------------- tensor-core GEMM: out = act([A1|A2] @ (Whi+Wlo) + b) ---------------
// Block: 64 rows x 64 cols, 128 threads (4 warps, 16 rows each). K = 128 (8 k-steps),
// mma.sync.m16n8k16 bf16, weights as hi+lo bf16 split for f32-level weight precision.
__global__ void __launch_bounds__(128) mma_gemm_kernel(
    const __nv_bfloat162* __restrict__ A1, const __nv_bfloat162* __restrict__ A2,
    const __nv_bfloat16* __restrict__ Whi, const __nv_bfloat16* __restrict__ Wlo,
    const float* __restrict__ bias, __nv_bfloat162* __restrict__ out, int do_relu) {
    __shared__ __align__(16) __nv_bfloat16 Ash[64 * 128];        // 16KB, 16 chunks/row
    __shared__ __align__(16) __nv_bfloat16 Wsh[2][128 * 64];     // 32KB, 8 chunks/row

    const int tid = threadIdx.x;
    const int lane = tid & 31;
    const int warp = tid >> 5;
    const int row_base = blockIdx.x * 64;

    // load A tile: 64 rows x 128 k (A1 k0-63 chunks0-7, A2 k64-127 chunks8-15)
    {
        int r = tid & 63;
        int half = tid >> 6;
        int grow = row_base + r;
        if (grow >= N_NODES) grow = N_NODES - 1;
        const uint4* src = reinterpret_cast<const uint4*>(
            (half ? A2 : A1) + (size_t)grow * 32);
        #pragma unroll
        for (int q = 0; q < 8; q++) {
            uint4 v = src[q];
            int chunk = half * 8 + q;
            int sw = (chunk & 8) | ((chunk ^ r) & 7);
            *reinterpret_cast<uint4*>(Ash + r * 128 + sw * 8) = v;
        }
    }
    // load W hi/lo: 2 x 128 rows x 8 chunks
    {
        #pragma unroll
        for (int q = 0; q < 16; q++) {
            int lin = q * 128 + tid;             // 0..2047
            int hl = lin >> 10;
            int rem = lin & 1023;
            int r = rem >> 3;
            int c = rem & 7;
            uint4 v = reinterpret_cast<const uint4*>((hl ? Wlo : Whi) + r * 64)[c];
            int sw = c ^ (r & 7);
            *reinterpret_cast<uint4*>(Wsh[hl] + r * 64 + sw * 8) = v;
        }
    }
    __syncthreads();

    float d[8][4];
    #pragma unroll
    for (int t = 0; t < 8; t++)
        #pragma unroll
        for (int q = 0; q < 4; q++) d[t][q] = 0.f;

    const int wrow = warp * 16;

    #pragma unroll
    for (int ks = 0; ks < 8; ks++) {
        // A fragment via ldmatrix.x4: lanes 0-15 rows 0-15 chunk ks*2, lanes 16-31 chunk ks*2+1
        uint32_t a0, a1, a2, a3;
        {
            int ar = wrow + (lane & 15);
            int ac = ks * 2 + (lane >> 4);
            int sw = (ac & 8) | ((ac ^ ar) & 7);
            uint32_t addr = su32(Ash + ar * 128 + sw * 8);
            asm volatile("ldmatrix.sync.aligned.m8n8.x4.shared.b16 {%0,%1,%2,%3}, [%4];"
                         : "=r"(a0), "=r"(a1), "=r"(a2), "=r"(a3) : "r"(addr));
        }
        #pragma unroll
        for (int hl = 0; hl < 2; hl++) {
            #pragma unroll
            for (int nt2 = 0; nt2 < 4; nt2++) {
                int krow = ks * 16 + (lane & 15);
                int c = nt2 * 2 + (lane >> 4);
                int sw = c ^ (krow & 7);
                uint32_t addr = su32(Wsh[hl] + krow * 64 + sw * 8);
                uint32_t b0, b1, b2, b3;
                asm volatile("ldmatrix.sync.aligned.m8n8.x4.trans.shared.b16 {%0,%1,%2,%3}, [%4];"
                             : "=r"(b0), "=r"(b1), "=r"(b2), "=r"(b3) : "r"(addr));
                asm volatile("mma.sync.aligned.m16n8k16.row.col.f32.bf16.bf16.f32 "
                             "{%0,%1,%2,%3},{%4,%5,%6,%7},{%8,%9},{%0,%1,%2,%3};"
                             : "+f"(d[nt2 * 2][0]), "+f"(d[nt2 * 2][1]),
                               "+f"(d[nt2 * 2][2]), "+f"(d[nt2 * 2][3])
                             : "r"(a0), "r"(a1), "r"(a2), "r"(a3), "r"(b0), "r"(b1));
                asm volatile("mma.sync.aligned.m16n8k16.row.col.f32.bf16.bf16.f32 "
                             "{%0,%1,%2,%3},{%4,%5,%6,%7},{%8,%9},{%0,%1,%2,%3};"
                             : "+f"(d[nt2 * 2 + 1][0]), "+f"(d[nt2 * 2 + 1][1]),
                               "+f"(d[nt2 * 2 + 1][2]), "+f"(d[nt2 * 2 + 1][3])
                             : "r"(a0), "r"(a1), "r"(a2), "r"(a3), "r"(b2), "r"(b3));
            }
        }
    }

    // epilogue: d[t][0,1] -> row wrow+g, cols 8t+2tg..+1; d[t][2,3] -> row wrow+8+g
    const int g = lane >> 2;
    const int tg = lane & 3;
    const int row0 = row_base + wrow + g;
    const int row1 = row0 + 8;
    #pragma unroll
    for (int t = 0; t < 8; t++) {
        int col = 8 * t + 2 * tg;
        float2 bv = *reinterpret_cast<const float2*>(bias + col);
        float o0 = d[t][0] + bv.x, o1 = d[t][1] + bv.y;
        float o2 = d[t][2] + bv.x, o3 = d[t][3] + bv.y;
        if (do_relu) {
            o0 = fmaxf(o0, 0.f); o1 = fmaxf(o1, 0.f);
            o2 = fmaxf(o2, 0.f); o3 = fmaxf(o3, 0.f);
        }
        if (row0 < N_NODES) {
            __nv_bfloat162 p = __float22bfloat162_rn(make_float2(o0, o1));
            out[(size_t)row0 * 32 + (col >> 1)] = p;
        }
        if (row1 < N_NODES) {
            __nv_bfloat162 p = __float22bfloat162_rn(make_float2(o2, o3));
            out[(size_t)row1 * 32 + (col >> 1)] = p;
        }
    }
}

// ---------------- layer 3 collapsed: sum_i outdeg[i]*(h2_i.wrel3) + (h2_i.wroot3) -----
__global__ void __launch_bounds__(256) final_kernel(const __nv_bfloat162* __restrict__ h2,
                                                    const int* __restrict__ deg,
                                                    const float* __restrict__ wrel3,
                                                    const float* __restrict__ wroot3,
                                                    double* __restrict__ red) {
    const int lane = threadIdx.x & 31;
    const int warp = threadIdx.x >> 5;
    const int gw = blockIdx.x * 8 + warp;
    const float2 wr = ((const float2*)wrel3)[lane];
    const float2 wo = ((const float2*)wroot3)[lane];

    float lv = 0.f;
    int i0 = gw * 16;
    int i1 = i0 + 16; if (i1 > N_NODES) i1 = N_NODES;
    for (int i = i0; i < i1; i++) {
        float2 a = __bfloat1622float2(h2[(size_t)i * 32 + lane]);
        float pv = a.x * wr.x + a.y * wr.y;
        float pu = a.x * wo.x + a.y * wo.y;
        lv += (float)__ldg(deg + i) * pv + pu;
    }
    #pragma unroll
    for (int off = 16; off; off >>= 1) lv += __shfl_xor_sync(0xffffffffu, lv, off);

    __shared__ double sh[8];
    if (lane == 0) sh[warp] = (double)lv;
    __syncthreads();
    if (threadIdx.x == 0) {
        double s = 0.0;
        #pragma unroll
        for (int w = 0; w < 8; w++) s += sh[w];
        atomicAdd(red, s);
    }
}

__global__ void write_out_kernel(float* __restrict__ out, const double* __restrict__ red,
                                 const float* __restrict__ b3) {
    if (threadIdx.x == 0 && blockIdx.x == 0)
        out[0] = (float)(red[0] / (double)N_NODES + (double)b3[0]);
}

// ---------------- launch ----------------
extern "C" void kernel_launch(void* const* d_in, const int* in_sizes, int n_in,
                              void* d_out, int out_size) {
    const float* x      = (const float*)d_in[0];
    const void*  ei     = d_in[1];
    const float* wrel1  = (const float*)d_in[2];
    const float* brel1  = (const float*)d_in[3];
    const float* wroot1 = (const float*)d_in[4];
    const float* wrel2  = (const float*)d_in[5];
    const float* brel2  = (const float*)d_in[6];
    const float* wroot2 = (const float*)d_in[7];
    const float* wrel3  = (const float*)d_in[8];
    const float* brel3  = (const float*)d_in[9];
    const float* wroot3 = (const float*)d_in[10];
    float* out = (float*)d_out;

    __nv_bfloat162 *xbf, *aggr, *h1, *h2;
    __nv_bfloat16 *whi, *wlo;
    int *csr, *indeg, *outdeg, *rowtmp, *rowptr, *cursor, *bsum, *is64;
    double* red;
    cudaGetSymbolAddress((void**)&xbf,    g_xbf);
    cudaGetSymbolAddress((void**)&aggr,   g_aggr);
    cudaGetSymbolAddress((void**)&h1,     g_h1);
    cudaGetSymbolAddress((void**)&h2,     g_h2);
    cudaGetSymbolAddress((void**)&whi,    g_whi);
    cudaGetSymbolAddress((void**)&wlo,    g_wlo);
    cudaGetSymbolAddress((void**)&csr,    g_csr);
    cudaGetSymbolAddress((void**)&indeg,  g_indeg);
    cudaGetSymbolAddress((void**)&outdeg, g_outdeg);
    cudaGetSymbolAddress((void**)&rowtmp, g_rowtmp);
    cudaGetSymbolAddress((void**)&rowptr, g_rowptr);
    cudaGetSymbolAddress((void**)&cursor, g_cursor);
    cudaGetSymbolAddress((void**)&bsum,   g_bsum);
    cudaGetSymbolAddress((void**)&red,    g_red);
    cudaGetSymbolAddress((void**)&is64,   g_is64);

    const int nblk = (N_NODES + 255) / 256;     // 391
    const int eblk = (N_EDGES + 255) / 256;     // 6250
    const int sblk = (N_NODES + 511) / 512;     // 196
    const int ablk = (N_NODES + 7) / 8;         // 12500
    const int gblk = (N_NODES + 63) / 64;       // 1563
    const int fblk = (N_NODES + 127) / 128;     // 782

    // prep + CSR build
    detect_kernel<<<1, 64>>>((const unsigned int*)ei, is64);
    zero_misc_kernel<<<nblk, 256>>>(indeg, outdeg, red);
    histconv_kernel<<<eblk, 256>>>(ei, x, xbf, indeg, outdeg, is64);
    wconv_kernel<<<64, 256>>>(wrel1, wroot1, wrel2, wroot2, whi, wlo);
    scan1_kernel<<<sblk, 512>>>(indeg, rowtmp, bsum);
    scan2_kernel<<<1, 256>>>(bsum, sblk);
    scan3_kernel<<<nblk, 256>>>(rowtmp, bsum, indeg, rowptr, cursor);
    fill_kernel<<<eblk, 256>>>(ei, cursor, csr, is64);

    // layer 1
    aggr_kernel<<<ablk, 256>>>(xbf, aggr, rowptr, csr);
    mma_gemm_kernel<<<gblk, 128>>>(aggr, xbf, whi, wlo, brel1, h1, 1);

    // layer 2
    aggr_kernel<<<ablk, 256>>>(h1, aggr, rowptr, csr);
    mma_gemm_kernel<<<gblk, 128>>>(aggr, h1, whi + 8192, wlo + 8192, brel2, h2, 1);

    // layer 3 collapsed into a degree-weighted reduction
    final_kernel<<<fblk, 256>>>(h2, outdeg, wrel3, wroot3, red);
    write_out_kernel<<<1, 32>>>(out, red, brel3);
}